// round 14
// baseline (speedup 1.0000x reference)
#include <cuda_runtime.h>
#include <cstdint>

// Problem constants
#define NROWS      524288
#define NCH        30
#define BLK_ROWS   256
#define THREADS    256
#define NBLOCKS    (NROWS / BLK_ROWS)     // 2048
#define CHUNK_ROWS 16
#define CHUNK_F4   (CHUNK_ROWS * 60)      // 960 float4 = 15360 B
#define NCHUNKS    (BLK_ROWS / CHUNK_ROWS) // 16
#define NBUF       3                       // 2 bulk stores outstanding per block

// Dynamic SMEM layout (floats, 16B-aligned sections):
//   sStage : NBUF * CHUNK_F4 * 4 = 11520 floats (46080 B)  @ 0
//   sV     : BLK_ROWS * 8        =  2048 floats (8192 B)
//   weights+TAB                  =   672 floats (2688 B)
#define OFF_STAGE   0
#define OFF_V       (NBUF * CHUNK_F4 * 4)            // 11520
#define OFF_W       (OFF_V + BLK_ROWS * 8)           // 13568
#define SMEM_FLOATS (OFF_W + 672)                    // 14240
#define SMEM_BYTES  (SMEM_FLOATS * 4)                // 56960

// FILTERS (6 x 30), compile-time constant from the reference
__constant__ float c_FILT[6 * 30] = {
    1,1,1,1,1,1,1,1,1,1,1,1,1,1,1,1,1,1,1,1,1,1,0,0,0,0,0,0,1,1,
    1,1,0,0,0,0,0,0,0,0,0,0,0,0,0,0,1,1,1,1,1,1,0,0,1,1,1,1,1,1,
    1,1,0,0,1,1,0,0,1,1,0,0,1,1,0,0,0,0,0,0,0,0,0,0,0,0,0,0,1,1,
    1,1,0,0,0,0,0,0,0,0,0,0,0,0,1,1,1,1,1,1,1,1,0,0,0,0,1,1,1,1,
    1,1,0,0,1,0,0,0,0,0,0,0,0,0,0,0,0,0,0,0,0,0,0,0,0,0,0,0,1,1,
    1,1,1,1,0,0,1,1,0,0,1,1,0,0,0,0,0,0,0,0,0,0,0,0,0,0,0,0,1,1
};

__device__ __forceinline__ void bulk_store(void* gptr, uint32_t smem_addr, uint32_t bytes) {
    asm volatile(
        "cp.async.bulk.global.shared::cta.bulk_group [%0], [%1], %2;"
        :: "l"(gptr), "r"(smem_addr), "r"(bytes) : "memory");
}

__global__ __launch_bounds__(THREADS, 4)
void ext_kernel(const float* __restrict__ tpl,   // (N,3)
                const float* __restrict__ cons,  // (N,8)
                const float* __restrict__ w_gas, // (8,30)
                const float* __restrict__ W1,    // (6,6,2)
                const float* __restrict__ b1,    // (6,6)
                const float* __restrict__ W2,    // (6,4,6)
                const float* __restrict__ b2,    // (6,4)
                const float* __restrict__ W3,    // (6,4,4)
                const float* __restrict__ b3,    // (6,4)
                const float* __restrict__ Wo,    // (6,4)
                const float* __restrict__ bo,    // (6,)
                float* __restrict__ out)         // (N,30,8)
{
    extern __shared__ __align__(16) float dsm[];
    float* sStageF = dsm + OFF_STAGE;
    float* sVF     = dsm + OFF_V;
    float* sW1 = dsm + OFF_W;        // 72
    float* sb1 = sW1 + 72;           // 36
    float* sW2 = sb1 + 36;           // 144
    float* sb2 = sW2 + 144;          // 24
    float* sW3 = sb2 + 24;           // 96
    float* sb3 = sW3 + 96;           // 24
    float* sWo = sb3 + 24;           // 24
    float* sbo = sWo + 24;           // 6 (+2 pad)
    float* sTAB = sbo + 8;           // 240, 16B-aligned (OFF_W+428? -> OFF_W=13568, +428 = 13996... )

    const int tid = threadIdx.x;

    // ---- stage weights + build TAB = exp(w_gas[j,ch]) * (j<2 ? 1 : FILT[j-2,ch]) ----
    if (tid < 144) sW2[tid] = W2[tid];
    if (tid < 96)  sW3[tid] = W3[tid];
    if (tid < 72)  sW1[tid] = W1[tid];
    if (tid < 36)  sb1[tid] = b1[tid];
    if (tid < 24)  { sb2[tid] = b2[tid]; sb3[tid] = b3[tid]; sWo[tid] = Wo[tid]; }
    if (tid < 6)   sbo[tid] = bo[tid];
    if (tid < 240) {
        int ch = tid >> 3, j = tid & 7;
        float e = __expf(w_gas[j * NCH + ch]);
        if (j >= 2) e *= c_FILT[(j - 2) * NCH + ch];
        sTAB[tid] = e;
    }

    // Per-thread staging constants: chunk = 4 slots of 256 float4 (last partial: 192)
    int srem[4], svi[4];
    #pragma unroll
    for (int c = 0; c < 4; c++) {
        const int idx = c * THREADS + tid;
        const int row = idx / 60;
        srem[c] = idx - row * 60;
        svi[c]  = row * 2 + (srem[c] & 1);
    }
    const bool act3 = tid < (CHUNK_F4 - 3 * THREADS);   // 960 - 768 = 192

    __syncthreads();

    // ---- phase 1: one thread per row: tiny MLPs -> s[6], fold into v[8] ----
    {
        const int n = blockIdx.x * BLK_ROWS + tid;
        const float t0 = tpl[n * 3 + 0];
        const float t1 = tpl[n * 3 + 1];
        const float4 c0 = reinterpret_cast<const float4*>(cons)[n * 2 + 0];
        const float4 c1 = reinterpret_cast<const float4*>(cons)[n * 2 + 1];

        float s[6];
        #pragma unroll
        for (int g = 0; g < 6; g++) {
            float h1[6];
            #pragma unroll
            for (int h = 0; h < 6; h++) {
                float a = fmaf(sW1[g*12 + h*2 + 0], t0,
                          fmaf(sW1[g*12 + h*2 + 1], t1, sb1[g*6 + h]));
                h1[h] = fmaxf(a, 0.0f);
            }
            float h2[4];
            #pragma unroll
            for (int o = 0; o < 4; o++) {
                float a = sb2[g*4 + o];
                #pragma unroll
                for (int h = 0; h < 6; h++) a = fmaf(sW2[g*24 + o*6 + h], h1[h], a);
                h2[o] = fmaxf(a, 0.0f);
            }
            float h3[4];
            #pragma unroll
            for (int p = 0; p < 4; p++) {
                float a = sb3[g*4 + p];
                #pragma unroll
                for (int h = 0; h < 4; h++) a = fmaf(sW3[g*16 + p*4 + h], h2[h], a);
                h3[p] = fmaxf(a, 0.0f);
            }
            float z = sbo[g];
            #pragma unroll
            for (int p = 0; p < 4; p++) z = fmaf(sWo[g*4 + p], h3[p], z);
            s[g] = __fdividef(1.0f, 1.0f + __expf(-z));   // sigmoid
        }

        float4* vw = reinterpret_cast<float4*>(sVF);
        vw[tid * 2 + 0] = make_float4(c0.x,        c0.y,        c0.z * s[0], c0.w * s[1]);
        vw[tid * 2 + 1] = make_float4(c1.x * s[2], c1.y * s[3], c1.z * s[4], c1.w * s[5]);
    }
    __syncthreads();

    // ---- phase 2: 16-row chunks (15360 B) via TMA, 3 buffers, 2 outstanding ----
    const float4* vb = reinterpret_cast<const float4*>(sVF);
    const float4* tb = reinterpret_cast<const float4*>(sTAB);
    char* gbase = reinterpret_cast<char*>(out) + (size_t)blockIdx.x * (BLK_ROWS * 960);

    for (int k = 0; k < NCHUNKS; k++) {
        const int buf = k % NBUF;
        if (k >= NBUF) {
            if (tid == 0)
                asm volatile("cp.async.bulk.wait_group.read %0;" :: "n"(NBUF - 1) : "memory");
            __syncthreads();   // buffer free for reuse
        }
        float4* st = reinterpret_cast<float4*>(sStageF) + buf * CHUNK_F4;
        const int vbase = k * (CHUNK_ROWS * 2);   // 32 float4 of sV per chunk
        #pragma unroll
        for (int c = 0; c < 4; c++) {
            if (c < 3 || act3) {
                float4 tab = tb[srem[c]];
                float4 vv  = vb[vbase + svi[c]];
                float4 r;
                r.x = vv.x * tab.x;
                r.y = vv.y * tab.y;
                r.z = vv.z * tab.z;
                r.w = vv.w * tab.w;
                st[c * THREADS + tid] = r;
            }
        }
        asm volatile("fence.proxy.async.shared::cta;" ::: "memory");
        __syncthreads();       // staging chunk complete
        if (tid == 0) {
            uint32_t saddr = (uint32_t)__cvta_generic_to_shared(st);
            bulk_store(gbase + (size_t)k * (CHUNK_ROWS * 960), saddr, CHUNK_ROWS * 960);
            asm volatile("cp.async.bulk.commit_group;" ::: "memory");
        }
    }
    if (tid == 0)
        asm volatile("cp.async.bulk.wait_group 0;" ::: "memory");
}

extern "C" void kernel_launch(void* const* d_in, const int* in_sizes, int n_in,
                              void* d_out, int out_size) {
    (void)in_sizes; (void)n_in; (void)out_size;
    static int smem_set = 0;
    if (!smem_set) {
        cudaFuncSetAttribute(ext_kernel,
                             cudaFuncAttributeMaxDynamicSharedMemorySize, SMEM_BYTES);
        smem_set = 1;
    }
    ext_kernel<<<NBLOCKS, THREADS, SMEM_BYTES>>>(
        (const float*)d_in[0],  // tpl
        (const float*)d_in[1],  // cons
        (const float*)d_in[2],  // w_gas
        (const float*)d_in[3],  // ke_W1
        (const float*)d_in[4],  // ke_b1
        (const float*)d_in[5],  // ke_W2
        (const float*)d_in[6],  // ke_b2
        (const float*)d_in[7],  // ke_W3
        (const float*)d_in[8],  // ke_b3
        (const float*)d_in[9],  // ke_Wo
        (const float*)d_in[10], // ke_bo
        (float*)d_out);
}

// round 15
// speedup vs baseline: 1.0597x; 1.0597x over previous
#include <cuda_runtime.h>
#include <cstdint>

// Problem constants
#define NROWS      524288
#define NCH        30
#define BLK_ROWS   256
#define THREADS    256
#define NBLOCKS    (NROWS / BLK_ROWS)     // 2048
#define CHUNK_ROWS 16
#define CHUNK_F4   (CHUNK_ROWS * 60)      // 960 float4 = 15360 B
#define NCHUNKS    (BLK_ROWS / CHUNK_ROWS) // 16
#define NBUF       2

// FILTERS (6 x 30), compile-time constant from the reference
__constant__ float c_FILT[6 * 30] = {
    1,1,1,1,1,1,1,1,1,1,1,1,1,1,1,1,1,1,1,1,1,1,0,0,0,0,0,0,1,1,
    1,1,0,0,0,0,0,0,0,0,0,0,0,0,0,0,1,1,1,1,1,1,0,0,1,1,1,1,1,1,
    1,1,0,0,1,1,0,0,1,1,0,0,1,1,0,0,0,0,0,0,0,0,0,0,0,0,0,0,1,1,
    1,1,0,0,0,0,0,0,0,0,0,0,0,0,1,1,1,1,1,1,1,1,0,0,0,0,1,1,1,1,
    1,1,0,0,1,0,0,0,0,0,0,0,0,0,0,0,0,0,0,0,0,0,0,0,0,0,0,0,1,1,
    1,1,1,1,0,0,1,1,0,0,1,1,0,0,0,0,0,0,0,0,0,0,0,0,0,0,0,0,1,1
};

__device__ __forceinline__ void bulk_store(void* gptr, uint32_t smem_addr, uint32_t bytes) {
    asm volatile(
        "cp.async.bulk.global.shared::cta.bulk_group [%0], [%1], %2;"
        :: "l"(gptr), "r"(smem_addr), "r"(bytes) : "memory");
}

__global__ __launch_bounds__(THREADS, 5)
void ext_kernel(const float* __restrict__ tpl,   // (N,3)
                const float* __restrict__ cons,  // (N,8)
                const float* __restrict__ w_gas, // (8,30)
                const float* __restrict__ W1,    // (6,6,2)
                const float* __restrict__ b1,    // (6,6)
                const float* __restrict__ W2,    // (6,4,6)
                const float* __restrict__ b2,    // (6,4)
                const float* __restrict__ W3,    // (6,4,4)
                const float* __restrict__ b3,    // (6,4)
                const float* __restrict__ Wo,    // (6,4)
                const float* __restrict__ bo,    // (6,)
                float* __restrict__ out)         // (N,30,8)
{
    __shared__ float sW1[72], sb1[36], sW2[144], sb2[24];
    __shared__ float sW3[96], sb3[24], sWo[24], sbo[6];
    __shared__ __align__(16) float sTAB[240];                // TAB[ch*8 + j]
    __shared__ __align__(16) float sV[BLK_ROWS * 8];         // v[row][8]
    __shared__ __align__(16) float4 sStage[NBUF][CHUNK_F4];  // 2 x 15360 B staging

    const int tid = threadIdx.x;

    // ---- stage weights + build TAB = exp(w_gas[j,ch]) * (j<2 ? 1 : FILT[j-2,ch]) ----
    if (tid < 144) sW2[tid] = W2[tid];
    if (tid < 96)  sW3[tid] = W3[tid];
    if (tid < 72)  sW1[tid] = W1[tid];
    if (tid < 36)  sb1[tid] = b1[tid];
    if (tid < 24)  { sb2[tid] = b2[tid]; sb3[tid] = b3[tid]; sWo[tid] = Wo[tid]; }
    if (tid < 6)   sbo[tid] = bo[tid];
    if (tid < 240) {
        int ch = tid >> 3, j = tid & 7;
        float e = __expf(w_gas[j * NCH + ch]);
        if (j >= 2) e *= c_FILT[(j - 2) * NCH + ch];
        sTAB[tid] = e;
    }

    // Per-thread staging constants: chunk = 4 slots of 256 float4 (last partial: 192)
    int srem[4], svi[4];
    #pragma unroll
    for (int c = 0; c < 4; c++) {
        const int idx = c * THREADS + tid;
        const int row = idx / 60;
        srem[c] = idx - row * 60;
        svi[c]  = row * 2 + (srem[c] & 1);
    }
    const bool act3 = tid < (CHUNK_F4 - 3 * THREADS);   // 960 - 768 = 192

    __syncthreads();

    // ---- phase 1: one thread per row: tiny MLPs -> s[6], fold into v[8] ----
    {
        const int n = blockIdx.x * BLK_ROWS + tid;
        const float t0 = tpl[n * 3 + 0];
        const float t1 = tpl[n * 3 + 1];
        const float4 c0 = reinterpret_cast<const float4*>(cons)[n * 2 + 0];
        const float4 c1 = reinterpret_cast<const float4*>(cons)[n * 2 + 1];

        float s[6];
        #pragma unroll
        for (int g = 0; g < 6; g++) {
            float h1[6];
            #pragma unroll
            for (int h = 0; h < 6; h++) {
                float a = fmaf(sW1[g*12 + h*2 + 0], t0,
                          fmaf(sW1[g*12 + h*2 + 1], t1, sb1[g*6 + h]));
                h1[h] = fmaxf(a, 0.0f);
            }
            float h2[4];
            #pragma unroll
            for (int o = 0; o < 4; o++) {
                float a = sb2[g*4 + o];
                #pragma unroll
                for (int h = 0; h < 6; h++) a = fmaf(sW2[g*24 + o*6 + h], h1[h], a);
                h2[o] = fmaxf(a, 0.0f);
            }
            float h3[4];
            #pragma unroll
            for (int p = 0; p < 4; p++) {
                float a = sb3[g*4 + p];
                #pragma unroll
                for (int h = 0; h < 4; h++) a = fmaf(sW3[g*16 + p*4 + h], h2[h], a);
                h3[p] = fmaxf(a, 0.0f);
            }
            float z = sbo[g];
            #pragma unroll
            for (int p = 0; p < 4; p++) z = fmaf(sWo[g*4 + p], h3[p], z);
            s[g] = __fdividef(1.0f, 1.0f + __expf(-z));   // sigmoid
        }

        float4* vw = reinterpret_cast<float4*>(sV);
        vw[tid * 2 + 0] = make_float4(c0.x,        c0.y,        c0.z * s[0], c0.w * s[1]);
        vw[tid * 2 + 1] = make_float4(c1.x * s[2], c1.y * s[3], c1.z * s[4], c1.w * s[5]);
    }
    __syncthreads();

    // ---- phase 2: 16-row chunks (15360 B) via TMA bulk stores, double buffered ----
    const float4* vb = reinterpret_cast<const float4*>(sV);
    const float4* tb = reinterpret_cast<const float4*>(sTAB);
    char* gbase = reinterpret_cast<char*>(out) + (size_t)blockIdx.x * (BLK_ROWS * 960);

    for (int k = 0; k < NCHUNKS; k++) {
        const int buf = k & 1;
        if (k >= NBUF) {
            if (tid == 0)
                asm volatile("cp.async.bulk.wait_group.read %0;" :: "n"(NBUF - 1) : "memory");
            __syncthreads();   // buffer free for reuse
        }
        float4* st = sStage[buf];
        const int vbase = k * (CHUNK_ROWS * 2);   // 32 float4 of sV per chunk
        #pragma unroll
        for (int c = 0; c < 4; c++) {
            if (c < 3 || act3) {
                float4 tab = tb[srem[c]];
                float4 vv  = vb[vbase + svi[c]];
                float4 r;
                r.x = vv.x * tab.x;
                r.y = vv.y * tab.y;
                r.z = vv.z * tab.z;
                r.w = vv.w * tab.w;
                st[c * THREADS + tid] = r;
            }
        }
        asm volatile("fence.proxy.async.shared::cta;" ::: "memory");
        __syncthreads();       // staging chunk complete
        if (tid == 0) {
            uint32_t saddr = (uint32_t)__cvta_generic_to_shared(st);
            bulk_store(gbase + (size_t)k * (CHUNK_ROWS * 960), saddr, CHUNK_ROWS * 960);
            asm volatile("cp.async.bulk.commit_group;" ::: "memory");
        }
    }
    if (tid == 0)
        asm volatile("cp.async.bulk.wait_group 0;" ::: "memory");
}

extern "C" void kernel_launch(void* const* d_in, const int* in_sizes, int n_in,
                              void* d_out, int out_size) {
    (void)in_sizes; (void)n_in; (void)out_size;
    ext_kernel<<<NBLOCKS, THREADS>>>(
        (const float*)d_in[0],  // tpl
        (const float*)d_in[1],  // cons
        (const float*)d_in[2],  // w_gas
        (const float*)d_in[3],  // ke_W1
        (const float*)d_in[4],  // ke_b1
        (const float*)d_in[5],  // ke_W2
        (const float*)d_in[6],  // ke_b2
        (const float*)d_in[7],  // ke_W3
        (const float*)d_in[8],  // ke_b3
        (const float*)d_in[9],  // ke_Wo
        (const float*)d_in[10], // ke_bo
        (float*)d_out);
}

// round 16
// speedup vs baseline: 1.0630x; 1.0031x over previous
#include <cuda_runtime.h>
#include <cstdint>

// Problem constants
#define NROWS      524288
#define NCH        30
#define BLK_ROWS   256
#define THREADS    256
#define NBLOCKS    (NROWS / BLK_ROWS)     // 2048
#define CHUNK_ROWS 16
#define CHUNK_F4   (CHUNK_ROWS * 60)      // 960 float4 = 15360 B
#define NCHUNKS    (BLK_ROWS / CHUNK_ROWS) // 16
#define NBUF       2

// FILTERS (6 x 30), compile-time constant from the reference
__constant__ float c_FILT[6 * 30] = {
    1,1,1,1,1,1,1,1,1,1,1,1,1,1,1,1,1,1,1,1,1,1,0,0,0,0,0,0,1,1,
    1,1,0,0,0,0,0,0,0,0,0,0,0,0,0,0,1,1,1,1,1,1,0,0,1,1,1,1,1,1,
    1,1,0,0,1,1,0,0,1,1,0,0,1,1,0,0,0,0,0,0,0,0,0,0,0,0,0,0,1,1,
    1,1,0,0,0,0,0,0,0,0,0,0,0,0,1,1,1,1,1,1,1,1,0,0,0,0,1,1,1,1,
    1,1,0,0,1,0,0,0,0,0,0,0,0,0,0,0,0,0,0,0,0,0,0,0,0,0,0,0,1,1,
    1,1,1,1,0,0,1,1,0,0,1,1,0,0,0,0,0,0,0,0,0,0,0,0,0,0,0,0,1,1
};

__device__ __forceinline__ void bulk_store(void* gptr, uint32_t smem_addr, uint32_t bytes) {
    asm volatile(
        "cp.async.bulk.global.shared::cta.bulk_group [%0], [%1], %2;"
        :: "l"(gptr), "r"(smem_addr), "r"(bytes) : "memory");
}

__global__ __launch_bounds__(THREADS, 5)
void ext_kernel(const float* __restrict__ tpl,   // (N,3)
                const float* __restrict__ cons,  // (N,8)
                const float* __restrict__ w_gas, // (8,30)
                const float* __restrict__ W1,    // (6,6,2)
                const float* __restrict__ b1,    // (6,6)
                const float* __restrict__ W2,    // (6,4,6)
                const float* __restrict__ b2,    // (6,4)
                const float* __restrict__ W3,    // (6,4,4)
                const float* __restrict__ b3,    // (6,4)
                const float* __restrict__ Wo,    // (6,4)
                const float* __restrict__ bo,    // (6,)
                float* __restrict__ out)         // (N,30,8)
{
    __shared__ float sW1[72], sb1[36], sW2[144], sb2[24];
    __shared__ float sW3[96], sb3[24], sWo[24], sbo[6];
    __shared__ __align__(16) float sTAB[240];                // TAB[ch*8 + j]
    __shared__ __align__(16) float sV[BLK_ROWS * 8];         // v[row][8]
    __shared__ __align__(16) float4 sStage[NBUF][CHUNK_F4];  // 2 x 15360 B staging

    const int tid = threadIdx.x;

    // ---- stage weights + build TAB = exp(w_gas[j,ch]) * (j<2 ? 1 : FILT[j-2,ch]) ----
    if (tid < 144) sW2[tid] = W2[tid];
    if (tid < 96)  sW3[tid] = W3[tid];
    if (tid < 72)  sW1[tid] = W1[tid];
    if (tid < 36)  sb1[tid] = b1[tid];
    if (tid < 24)  { sb2[tid] = b2[tid]; sb3[tid] = b3[tid]; sWo[tid] = Wo[tid]; }
    if (tid < 6)   sbo[tid] = bo[tid];
    if (tid < 240) {
        int ch = tid >> 3, j = tid & 7;
        float e = __expf(w_gas[j * NCH + ch]);
        if (j >= 2) e *= c_FILT[(j - 2) * NCH + ch];
        sTAB[tid] = e;
    }

    // Per-thread staging constants: chunk = 4 slots of 256 float4 (last partial: 192)
    int srem[4], svi[4];
    #pragma unroll
    for (int c = 0; c < 4; c++) {
        const int idx = c * THREADS + tid;
        const int row = idx / 60;
        srem[c] = idx - row * 60;
        svi[c]  = row * 2 + (srem[c] & 1);
    }
    const bool act3 = tid < (CHUNK_F4 - 3 * THREADS);   // 960 - 768 = 192

    __syncthreads();

    // ---- phase 1: one thread per row: tiny MLPs -> s[6], fold into v[8] ----
    {
        const int n = blockIdx.x * BLK_ROWS + tid;
        const float t0 = tpl[n * 3 + 0];
        const float t1 = tpl[n * 3 + 1];
        const float4 c0 = reinterpret_cast<const float4*>(cons)[n * 2 + 0];
        const float4 c1 = reinterpret_cast<const float4*>(cons)[n * 2 + 1];

        float s[6];
        #pragma unroll
        for (int g = 0; g < 6; g++) {
            float h1[6];
            #pragma unroll
            for (int h = 0; h < 6; h++) {
                float a = fmaf(sW1[g*12 + h*2 + 0], t0,
                          fmaf(sW1[g*12 + h*2 + 1], t1, sb1[g*6 + h]));
                h1[h] = fmaxf(a, 0.0f);
            }
            float h2[4];
            #pragma unroll
            for (int o = 0; o < 4; o++) {
                float a = sb2[g*4 + o];
                #pragma unroll
                for (int h = 0; h < 6; h++) a = fmaf(sW2[g*24 + o*6 + h], h1[h], a);
                h2[o] = fmaxf(a, 0.0f);
            }
            float h3[4];
            #pragma unroll
            for (int p = 0; p < 4; p++) {
                float a = sb3[g*4 + p];
                #pragma unroll
                for (int h = 0; h < 4; h++) a = fmaf(sW3[g*16 + p*4 + h], h2[h], a);
                h3[p] = fmaxf(a, 0.0f);
            }
            float z = sbo[g];
            #pragma unroll
            for (int p = 0; p < 4; p++) z = fmaf(sWo[g*4 + p], h3[p], z);
            s[g] = __fdividef(1.0f, 1.0f + __expf(-z));   // sigmoid
        }

        float4* vw = reinterpret_cast<float4*>(sV);
        vw[tid * 2 + 0] = make_float4(c0.x,        c0.y,        c0.z * s[0], c0.w * s[1]);
        vw[tid * 2 + 1] = make_float4(c1.x * s[2], c1.y * s[3], c1.z * s[4], c1.w * s[5]);
    }
    __syncthreads();

    // ---- phase 2: 16-row chunks (15360 B) via TMA bulk stores, double buffered ----
    const float4* vb = reinterpret_cast<const float4*>(sV);
    const float4* tb = reinterpret_cast<const float4*>(sTAB);
    char* gbase = reinterpret_cast<char*>(out) + (size_t)blockIdx.x * (BLK_ROWS * 960);

    for (int k = 0; k < NCHUNKS; k++) {
        const int buf = k & 1;
        if (k >= NBUF) {
            if (tid == 0)
                asm volatile("cp.async.bulk.wait_group.read %0;" :: "n"(NBUF - 1) : "memory");
            __syncthreads();   // buffer free for reuse
        }
        float4* st = sStage[buf];
        const int vbase = k * (CHUNK_ROWS * 2);   // 32 float4 of sV per chunk
        #pragma unroll
        for (int c = 0; c < 4; c++) {
            if (c < 3 || act3) {
                float4 tab = tb[srem[c]];
                float4 vv  = vb[vbase + svi[c]];
                float4 r;
                r.x = vv.x * tab.x;
                r.y = vv.y * tab.y;
                r.z = vv.z * tab.z;
                r.w = vv.w * tab.w;
                st[c * THREADS + tid] = r;
            }
        }
        asm volatile("fence.proxy.async.shared::cta;" ::: "memory");
        __syncthreads();       // staging chunk complete
        if (tid == 0) {
            uint32_t saddr = (uint32_t)__cvta_generic_to_shared(st);
            bulk_store(gbase + (size_t)k * (CHUNK_ROWS * 960), saddr, CHUNK_ROWS * 960);
            asm volatile("cp.async.bulk.commit_group;" ::: "memory");
        }
    }
    if (tid == 0)
        asm volatile("cp.async.bulk.wait_group 0;" ::: "memory");
}

extern "C" void kernel_launch(void* const* d_in, const int* in_sizes, int n_in,
                              void* d_out, int out_size) {
    (void)in_sizes; (void)n_in; (void)out_size;
    ext_kernel<<<NBLOCKS, THREADS>>>(
        (const float*)d_in[0],  // tpl
        (const float*)d_in[1],  // cons
        (const float*)d_in[2],  // w_gas
        (const float*)d_in[3],  // ke_W1
        (const float*)d_in[4],  // ke_b1
        (const float*)d_in[5],  // ke_W2
        (const float*)d_in[6],  // ke_b2
        (const float*)d_in[7],  // ke_W3
        (const float*)d_in[8],  // ke_b3
        (const float*)d_in[9],  // ke_Wo
        (const float*)d_in[10], // ke_bo
        (float*)d_out);
}

// round 17
// speedup vs baseline: 1.1514x; 1.0832x over previous
#include <cuda_runtime.h>
#include <cstdint>

// Problem constants
#define NROWS      524288
#define NCH        30
#define BLK_ROWS   256
#define THREADS    256
#define NBLOCKS    (NROWS / BLK_ROWS)     // 2048
#define CHUNK_ROWS 16
#define CHUNK_F4   (CHUNK_ROWS * 60)      // 960 float4 = 15360 B
#define NCHUNKS    (BLK_ROWS / CHUNK_ROWS) // 16
#define NBUF       2

// FILTERS (6 x 30), compile-time constant from the reference
__constant__ float c_FILT[6 * 30] = {
    1,1,1,1,1,1,1,1,1,1,1,1,1,1,1,1,1,1,1,1,1,1,0,0,0,0,0,0,1,1,
    1,1,0,0,0,0,0,0,0,0,0,0,0,0,0,0,1,1,1,1,1,1,0,0,1,1,1,1,1,1,
    1,1,0,0,1,1,0,0,1,1,0,0,1,1,0,0,0,0,0,0,0,0,0,0,0,0,0,0,1,1,
    1,1,0,0,0,0,0,0,0,0,0,0,0,0,1,1,1,1,1,1,1,1,0,0,0,0,1,1,1,1,
    1,1,0,0,1,0,0,0,0,0,0,0,0,0,0,0,0,0,0,0,0,0,0,0,0,0,0,0,1,1,
    1,1,1,1,0,0,1,1,0,0,1,1,0,0,0,0,0,0,0,0,0,0,0,0,0,0,0,0,1,1
};

// Bulk store with L2 evict-first hint: output is write-once, never re-read.
__device__ __forceinline__ void bulk_store_ef(void* gptr, uint32_t smem_addr,
                                              uint32_t bytes, uint64_t policy) {
    asm volatile(
        "cp.async.bulk.global.shared::cta.bulk_group.L2::cache_hint [%0], [%1], %2, %3;"
        :: "l"(gptr), "r"(smem_addr), "r"(bytes), "l"(policy) : "memory");
}

__global__ __launch_bounds__(THREADS, 5)
void ext_kernel(const float* __restrict__ tpl,   // (N,3)
                const float* __restrict__ cons,  // (N,8)
                const float* __restrict__ w_gas, // (8,30)
                const float* __restrict__ W1,    // (6,6,2)
                const float* __restrict__ b1,    // (6,6)
                const float* __restrict__ W2,    // (6,4,6)
                const float* __restrict__ b2,    // (6,4)
                const float* __restrict__ W3,    // (6,4,4)
                const float* __restrict__ b3,    // (6,4)
                const float* __restrict__ Wo,    // (6,4)
                const float* __restrict__ bo,    // (6,)
                float* __restrict__ out)         // (N,30,8)
{
    __shared__ float sW1[72], sb1[36], sW2[144], sb2[24];
    __shared__ float sW3[96], sb3[24], sWo[24], sbo[6];
    __shared__ __align__(16) float sTAB[240];                // TAB[ch*8 + j]
    __shared__ __align__(16) float sV[BLK_ROWS * 8];         // v[row][8]
    __shared__ __align__(16) float4 sStage[NBUF][CHUNK_F4];  // 2 x 15360 B staging

    const int tid = threadIdx.x;

    // ---- stage weights + build TAB = exp(w_gas[j,ch]) * (j<2 ? 1 : FILT[j-2,ch]) ----
    if (tid < 144) sW2[tid] = W2[tid];
    if (tid < 96)  sW3[tid] = W3[tid];
    if (tid < 72)  sW1[tid] = W1[tid];
    if (tid < 36)  sb1[tid] = b1[tid];
    if (tid < 24)  { sb2[tid] = b2[tid]; sb3[tid] = b3[tid]; sWo[tid] = Wo[tid]; }
    if (tid < 6)   sbo[tid] = bo[tid];
    if (tid < 240) {
        int ch = tid >> 3, j = tid & 7;
        float e = __expf(w_gas[j * NCH + ch]);
        if (j >= 2) e *= c_FILT[(j - 2) * NCH + ch];
        sTAB[tid] = e;
    }

    // Per-thread staging constants: chunk = 4 slots of 256 float4 (last partial: 192)
    int srem[4], svi[4];
    #pragma unroll
    for (int c = 0; c < 4; c++) {
        const int idx = c * THREADS + tid;
        const int row = idx / 60;
        srem[c] = idx - row * 60;
        svi[c]  = row * 2 + (srem[c] & 1);
    }
    const bool act3 = tid < (CHUNK_F4 - 3 * THREADS);   // 960 - 768 = 192

    // Evict-first allocation policy for the streamed output
    uint64_t pol;
    asm volatile("createpolicy.fractional.L2::evict_first.b64 %0, 1.0;" : "=l"(pol));

    __syncthreads();

    // ---- phase 1: one thread per row: tiny MLPs -> s[6], fold into v[8] ----
    {
        const int n = blockIdx.x * BLK_ROWS + tid;
        const float t0 = tpl[n * 3 + 0];
        const float t1 = tpl[n * 3 + 1];
        const float4 c0 = reinterpret_cast<const float4*>(cons)[n * 2 + 0];
        const float4 c1 = reinterpret_cast<const float4*>(cons)[n * 2 + 1];

        float s[6];
        #pragma unroll
        for (int g = 0; g < 6; g++) {
            float h1[6];
            #pragma unroll
            for (int h = 0; h < 6; h++) {
                float a = fmaf(sW1[g*12 + h*2 + 0], t0,
                          fmaf(sW1[g*12 + h*2 + 1], t1, sb1[g*6 + h]));
                h1[h] = fmaxf(a, 0.0f);
            }
            float h2[4];
            #pragma unroll
            for (int o = 0; o < 4; o++) {
                float a = sb2[g*4 + o];
                #pragma unroll
                for (int h = 0; h < 6; h++) a = fmaf(sW2[g*24 + o*6 + h], h1[h], a);
                h2[o] = fmaxf(a, 0.0f);
            }
            float h3[4];
            #pragma unroll
            for (int p = 0; p < 4; p++) {
                float a = sb3[g*4 + p];
                #pragma unroll
                for (int h = 0; h < 4; h++) a = fmaf(sW3[g*16 + p*4 + h], h2[h], a);
                h3[p] = fmaxf(a, 0.0f);
            }
            float z = sbo[g];
            #pragma unroll
            for (int p = 0; p < 4; p++) z = fmaf(sWo[g*4 + p], h3[p], z);
            s[g] = __fdividef(1.0f, 1.0f + __expf(-z));   // sigmoid
        }

        float4* vw = reinterpret_cast<float4*>(sV);
        vw[tid * 2 + 0] = make_float4(c0.x,        c0.y,        c0.z * s[0], c0.w * s[1]);
        vw[tid * 2 + 1] = make_float4(c1.x * s[2], c1.y * s[3], c1.z * s[4], c1.w * s[5]);
    }
    __syncthreads();

    // ---- phase 2: 16-row chunks (15360 B) via TMA bulk stores, double buffered ----
    const float4* vb = reinterpret_cast<const float4*>(sV);
    const float4* tb = reinterpret_cast<const float4*>(sTAB);
    char* gbase = reinterpret_cast<char*>(out) + (size_t)blockIdx.x * (BLK_ROWS * 960);

    for (int k = 0; k < NCHUNKS; k++) {
        const int buf = k & 1;
        if (k >= NBUF) {
            if (tid == 0)
                asm volatile("cp.async.bulk.wait_group.read %0;" :: "n"(NBUF - 1) : "memory");
            __syncthreads();   // buffer free for reuse
        }
        float4* st = sStage[buf];
        const int vbase = k * (CHUNK_ROWS * 2);   // 32 float4 of sV per chunk
        #pragma unroll
        for (int c = 0; c < 4; c++) {
            if (c < 3 || act3) {
                float4 tab = tb[srem[c]];
                float4 vv  = vb[vbase + svi[c]];
                float4 r;
                r.x = vv.x * tab.x;
                r.y = vv.y * tab.y;
                r.z = vv.z * tab.z;
                r.w = vv.w * tab.w;
                st[c * THREADS + tid] = r;
            }
        }
        asm volatile("fence.proxy.async.shared::cta;" ::: "memory");
        __syncthreads();       // staging chunk complete
        if (tid == 0) {
            uint32_t saddr = (uint32_t)__cvta_generic_to_shared(st);
            bulk_store_ef(gbase + (size_t)k * (CHUNK_ROWS * 960), saddr,
                          CHUNK_ROWS * 960, pol);
            asm volatile("cp.async.bulk.commit_group;" ::: "memory");
        }
    }
    if (tid == 0)
        asm volatile("cp.async.bulk.wait_group 0;" ::: "memory");
}

extern "C" void kernel_launch(void* const* d_in, const int* in_sizes, int n_in,
                              void* d_out, int out_size) {
    (void)in_sizes; (void)n_in; (void)out_size;
    ext_kernel<<<NBLOCKS, THREADS>>>(
        (const float*)d_in[0],  // tpl
        (const float*)d_in[1],  // cons
        (const float*)d_in[2],  // w_gas
        (const float*)d_in[3],  // ke_W1
        (const float*)d_in[4],  // ke_b1
        (const float*)d_in[5],  // ke_W2
        (const float*)d_in[6],  // ke_b2
        (const float*)d_in[7],  // ke_W3
        (const float*)d_in[8],  // ke_b3
        (const float*)d_in[9],  // ke_Wo
        (const float*)d_in[10], // ke_bo
        (float*)d_out);
}